// round 13
// baseline (speedup 1.0000x reference)
#include <cuda_runtime.h>
#include <cuda_fp16.h>
#include <math.h>
#include <stdint.h>

#define SL   4096
#define DIM  2048
#define NH   8
#define NKV  2
#define HDIM 256
#define WIN  512
#define KVD  512
#define QKVN 3072   // packed Q|K|V output width

// ---------------- scratch ----------------
__device__ __half g_xh[SL * DIM],  g_xl[SL * DIM];
__device__ __half g_qh[SL * DIM],  g_ql[SL * DIM];
__device__ __half g_kh[SL * KVD],  g_kl[SL * KVD];
__device__ __half g_vh[SL * KVD];
__device__ __half g_ah[SL * DIM];
__device__ __half g_wh[QKVN * DIM], g_wl[QKVN * DIM];   // packed Wq|Wk|Wv (transposed)
__device__ __half g_woh[DIM * DIM];
__device__ float  g_sin[SL * 128], g_cos[SL * 128];

__device__ __forceinline__ uint32_t smem_u32(const void* p) {
    uint32_t a;
    asm("{ .reg .u64 t; cvta.to.shared.u64 t, %1; cvt.u32.u64 %0, t; }" : "=r"(a) : "l"(p));
    return a;
}
__device__ __forceinline__ void cp16(uint32_t dst, const void* src) {
    asm volatile("cp.async.cg.shared.global [%0], [%1], 16;" :: "r"(dst), "l"(src) : "memory");
}
__device__ __forceinline__ void ldm4(uint32_t a, uint32_t r[4]) {
    asm volatile("ldmatrix.sync.aligned.m8n8.x4.shared.b16 {%0,%1,%2,%3}, [%4];"
                 : "=r"(r[0]), "=r"(r[1]), "=r"(r[2]), "=r"(r[3]) : "r"(a));
}
__device__ __forceinline__ void ldm4t(uint32_t a, uint32_t r[4]) {
    asm volatile("ldmatrix.sync.aligned.m8n8.x4.trans.shared.b16 {%0,%1,%2,%3}, [%4];"
                 : "=r"(r[0]), "=r"(r[1]), "=r"(r[2]), "=r"(r[3]) : "r"(a));
}
__device__ __forceinline__ void mma_h(float c[4], const uint32_t a[4], uint32_t b0, uint32_t b1) {
    asm volatile("mma.sync.aligned.m16n8k16.row.col.f32.f16.f16.f32 "
                 "{%0,%1,%2,%3}, {%4,%5,%6,%7}, {%8,%9}, {%0,%1,%2,%3};"
                 : "+f"(c[0]), "+f"(c[1]), "+f"(c[2]), "+f"(c[3])
                 : "r"(a[0]), "r"(a[1]), "r"(a[2]), "r"(a[3]), "r"(b0), "r"(b1));
}

// ---------------- conversion / table kernels ----------------
__global__ void split_kernel(const float* __restrict__ src,
                             __half* __restrict__ hi, __half* __restrict__ lo, int n4) {
    int i = blockIdx.x * blockDim.x + threadIdx.x;
    if (i >= n4) return;
    float4 v = ((const float4*)src)[i];
    float f[4] = {v.x, v.y, v.z, v.w};
    __half h[4], l[4];
    #pragma unroll
    for (int j = 0; j < 4; j++) {
        h[j] = __float2half(f[j]);
        l[j] = __float2half(f[j] - __half2float(h[j]));
    }
    __half2* h2 = (__half2*)hi;
    __half2* l2 = (__half2*)lo;
    h2[2 * i + 0] = __halves2half2(h[0], h[1]);
    h2[2 * i + 1] = __halves2half2(h[2], h[3]);
    l2[2 * i + 0] = __halves2half2(l[0], l[1]);
    l2[2 * i + 1] = __halves2half2(l[2], l[3]);
}

template<bool WLO>
__global__ void splitT_kernel(const float* __restrict__ src,
                              __half* __restrict__ hi, __half* __restrict__ lo, int K, int N) {
    __shared__ float t[32][33];
    const int tx = threadIdx.x, ty = threadIdx.y;
    const int n0 = blockIdx.x * 32, k0 = blockIdx.y * 32;
    #pragma unroll
    for (int i = 0; i < 32; i += 8)
        t[ty + i][tx] = src[(size_t)(k0 + ty + i) * N + n0 + tx];
    __syncthreads();
    #pragma unroll
    for (int i = 0; i < 32; i += 8) {
        float v = t[tx][ty + i];
        __half h = __float2half(v);
        size_t o = (size_t)(n0 + ty + i) * K + k0 + tx;
        hi[o] = h;
        if (WLO) lo[o] = __float2half(v - __half2float(h));
    }
}

__global__ void rope_table_kernel(const int* __restrict__ positions) {
    int idx = blockIdx.x * 256 + threadIdx.x;   // [0, SL*128)
    int t   = idx & 127;
    int tok = idx >> 7;
    float pos = (float)positions[tok];
    float timescale = powf(10000.0f, (float)t * (1.0f / 128.0f));
    float sv, cv;
    sincosf(pos / timescale, &sv, &cv);
    g_sin[idx] = sv;
    g_cos[idx] = cv;
}

// ---------------- fp16 mma GEMM: C[M,N] = A[M,2048] @ B[N,2048]^T ----------------
// 128x256 block tile, 8 warps (2m x 4n, 64x64 each), K-chunk 64, 2-stage cp.async.
// FUSE=true: epilogue does per-head RMSNorm + RoPE + fp16 hi/lo split (QKV path).
#define GBK 64

template<int TERMS>
__device__ __forceinline__ void gh_load(uint32_t st,
                                        const __half* __restrict__ Ah, const __half* __restrict__ Al,
                                        const __half* __restrict__ Bh, const __half* __restrict__ Bl,
                                        int m0, int n0, int kc) {
    constexpr int AOFFL = 18432;
    constexpr int BOFF  = (TERMS == 3) ? 36864 : 18432;
    constexpr int BOFFL = 73728;
    const int tid = threadIdx.x;
    #pragma unroll
    for (int it = 0; it < 4; it++) {
        int u = it * 256 + tid, row = u >> 3, cb = (u & 7) * 16;
        cp16(st + row * 144 + cb, (const char*)(Ah + (size_t)(m0 + row) * DIM + kc) + cb);
        if (TERMS == 3)
            cp16(st + AOFFL + row * 144 + cb, (const char*)(Al + (size_t)(m0 + row) * DIM + kc) + cb);
    }
    #pragma unroll
    for (int it = 0; it < 8; it++) {
        int u = it * 256 + tid, row = u >> 3, cb = (u & 7) * 16;
        cp16(st + BOFF + row * 144 + cb, (const char*)(Bh + (size_t)(n0 + row) * DIM + kc) + cb);
        if (TERMS == 3)
            cp16(st + BOFFL + row * 144 + cb, (const char*)(Bl + (size_t)(n0 + row) * DIM + kc) + cb);
    }
}

template<int TERMS, bool FUSE>
__global__ __launch_bounds__(256, 1)
void gemm_h(const __half* __restrict__ Ah, const __half* __restrict__ Al,
            const __half* __restrict__ Bh, const __half* __restrict__ Bl,
            float* __restrict__ C, int Nld,
            const int* __restrict__ positions,
            const float* __restrict__ q_scale, const float* __restrict__ k_scale) {
    constexpr int AOFFL = 18432;
    constexpr int BOFF  = (TERMS == 3) ? 36864 : 18432;
    constexpr int BOFFL = 73728;
    constexpr int STG   = (TERMS == 3) ? 110592 : 55296;
    extern __shared__ char smem[];
    const uint32_t sb = smem_u32(smem);
    const int tid = threadIdx.x, lane = tid & 31, w = tid >> 5;
    const int wmi = w >> 2, wni = w & 3;
    const int m0 = blockIdx.y * 128, n0 = blockIdx.x * 256;

    uint32_t a_off[4], b_off[4];
    #pragma unroll
    for (int mi = 0; mi < 4; mi++)
        a_off[mi] = (uint32_t)((wmi * 64 + mi * 16 + (lane & 15)) * 144 + ((lane >> 4) << 4));
    #pragma unroll
    for (int ni = 0; ni < 4; ni++)
        b_off[ni] = (uint32_t)((wni * 64 + ni * 16 + (lane & 7) + ((lane >> 4) << 3)) * 144
                               + (((lane >> 3) & 1) << 4));

    float acc[4][8][4];
    #pragma unroll
    for (int mi = 0; mi < 4; mi++)
        #pragma unroll
        for (int nj = 0; nj < 8; nj++)
            #pragma unroll
            for (int e = 0; e < 4; e++) acc[mi][nj][e] = 0.0f;

    const int nch = DIM / GBK;   // 32

    gh_load<TERMS>(sb, Ah, Al, Bh, Bl, m0, n0, 0);
    asm volatile("cp.async.commit_group;" ::: "memory");
    gh_load<TERMS>(sb + STG, Ah, Al, Bh, Bl, m0, n0, GBK);
    asm volatile("cp.async.commit_group;" ::: "memory");

    for (int c = 0; c < nch; c++) {
        if (c == nch - 1) asm volatile("cp.async.wait_group 0;" ::: "memory");
        else              asm volatile("cp.async.wait_group 1;" ::: "memory");
        __syncthreads();

        const uint32_t st = sb + (uint32_t)(c & 1) * STG;

        #pragma unroll
        for (int ks = 0; ks < 4; ks++) {
            const uint32_t kb = (uint32_t)(ks * 32);
            uint32_t ah[4][4], bh[4][4];
            uint32_t al[4][4], bl[4][4];
            #pragma unroll
            for (int mi = 0; mi < 4; mi++) {
                ldm4(st + a_off[mi] + kb, ah[mi]);
                if (TERMS == 3) ldm4(st + AOFFL + a_off[mi] + kb, al[mi]);
            }
            #pragma unroll
            for (int ni = 0; ni < 4; ni++) {
                ldm4(st + BOFF + b_off[ni] + kb, bh[ni]);
                if (TERMS == 3) ldm4(st + BOFFL + b_off[ni] + kb, bl[ni]);
            }
            #pragma unroll
            for (int mi = 0; mi < 4; mi++)
                #pragma unroll
                for (int ni = 0; ni < 4; ni++) {
                    mma_h(acc[mi][ni * 2 + 0], ah[mi], bh[ni][0], bh[ni][1]);
                    mma_h(acc[mi][ni * 2 + 1], ah[mi], bh[ni][2], bh[ni][3]);
                    if (TERMS == 3) {
                        mma_h(acc[mi][ni * 2 + 0], al[mi], bh[ni][0], bh[ni][1]);
                        mma_h(acc[mi][ni * 2 + 1], al[mi], bh[ni][2], bh[ni][3]);
                        mma_h(acc[mi][ni * 2 + 0], ah[mi], bl[ni][0], bl[ni][1]);
                        mma_h(acc[mi][ni * 2 + 1], ah[mi], bl[ni][2], bl[ni][3]);
                    }
                }
        }
        __syncthreads();
        if (c + 2 < nch) {
            gh_load<TERMS>(sb + (uint32_t)(c & 1) * STG, Ah, Al, Bh, Bl, m0, n0, (c + 2) * GBK);
            asm volatile("cp.async.commit_group;" ::: "memory");
        }
    }

    if (!FUSE) {
        const int mbase = m0 + wmi * 64 + (lane >> 2);
        const int nbase = n0 + wni * 64 + (lane & 3) * 2;
        #pragma unroll
        for (int mi = 0; mi < 4; mi++)
            #pragma unroll
            for (int nj = 0; nj < 8; nj++) {
                float* p0 = C + (size_t)(mbase + mi * 16) * Nld + nbase + nj * 8;
                float* p1 = C + (size_t)(mbase + mi * 16 + 8) * Nld + nbase + nj * 8;
                *(float2*)p0 = make_float2(acc[mi][nj][0], acc[mi][nj][1]);
                *(float2*)p1 = make_float2(acc[mi][nj][2], acc[mi][nj][3]);
            }
        return;
    }

    // ================= fused epilogue: RMSNorm (+scale) + RoPE + hi/lo split ====
    // This CTA owns one complete head: rows m0..m0+127, head-cols 0..255.
    // Tile type by n0: [0,2048)=Q, [2048,2560)=K, [2560,3072)=V.
    const bool isQ = (n0 < 2048);
    const bool isV = (n0 >= 2560);
    float* buf  = (float*)smem;                         // [128][257] fp32
    float* sred = (float*)(smem + 132096);              // [4][128]

    // --- per-row sum of squares ---
    const int rloc = wmi * 64 + (lane >> 2);            // + mi*16 (+8)
    float rsq[4][2];
    #pragma unroll
    for (int mi = 0; mi < 4; mi++) {
        rsq[mi][0] = 0.0f; rsq[mi][1] = 0.0f;
        #pragma unroll
        for (int nj = 0; nj < 8; nj++) {
            rsq[mi][0] += acc[mi][nj][0] * acc[mi][nj][0] + acc[mi][nj][1] * acc[mi][nj][1];
            rsq[mi][1] += acc[mi][nj][2] * acc[mi][nj][2] + acc[mi][nj][3] * acc[mi][nj][3];
        }
        #pragma unroll
        for (int off = 1; off < 4; off <<= 1) {
            rsq[mi][0] += __shfl_xor_sync(0xffffffffu, rsq[mi][0], off);
            rsq[mi][1] += __shfl_xor_sync(0xffffffffu, rsq[mi][1], off);
        }
    }
    __syncthreads();   // smem stage data dead; safe to reuse
    if ((lane & 3) == 0) {
        #pragma unroll
        for (int mi = 0; mi < 4; mi++) {
            sred[wni * 128 + rloc + mi * 16]     = rsq[mi][0];
            sred[wni * 128 + rloc + mi * 16 + 8] = rsq[mi][1];
        }
    }
    __syncthreads();

    float inv[4][2];
    #pragma unroll
    for (int mi = 0; mi < 4; mi++)
        #pragma unroll
        for (int p = 0; p < 2; p++) {
            int r = rloc + mi * 16 + p * 8;
            float tot = sred[r] + sred[128 + r] + sred[256 + r] + sred[384 + r];
            inv[mi][p] = rsqrtf(tot * (1.0f / 256.0f) + 1e-6f);
        }

    // --- scale factors for this thread's 16 cols ---
    const int cbase = wni * 64 + (lane & 3) * 2;        // head-col base; + nj*8 + e
    float scl[8][2];
    #pragma unroll
    for (int nj = 0; nj < 8; nj++) {
        if (isV) { scl[nj][0] = 1.0f; scl[nj][1] = 1.0f; }
        else {
            const float* sc = isQ ? q_scale : k_scale;
            scl[nj][0] = sc[cbase + nj * 8];
            scl[nj][1] = sc[cbase + nj * 8 + 1];
        }
    }

    // --- output base pointers ---
    __half *outH, *outL = nullptr;
    int ostride, obase;
    if (isQ)      { outH = g_qh; outL = g_ql; ostride = DIM; obase = n0; }
    else if (isV) { outH = g_vh;              ostride = KVD; obase = n0 - 2560; }
    else          { outH = g_kh; outL = g_kl; ostride = KVD; obase = n0 - 2048; }

    if (isV) {
        // no rope: direct split/store
        #pragma unroll
        for (int mi = 0; mi < 4; mi++)
            #pragma unroll
            for (int p = 0; p < 2; p++) {
                int row = rloc + mi * 16 + p * 8;
                size_t ob = (size_t)(m0 + row) * ostride + obase + cbase;
                #pragma unroll
                for (int nj = 0; nj < 8; nj++) {
                    float v0 = acc[mi][nj][p * 2]     * inv[mi][p];
                    float v1 = acc[mi][nj][p * 2 + 1] * inv[mi][p];
                    *(__half2*)(outH + ob + nj * 8) =
                        __halves2half2(__float2half(v0), __float2half(v1));
                }
            }
        return;
    }

    // rope path: write normed+scaled values to buf
    #pragma unroll
    for (int mi = 0; mi < 4; mi++)
        #pragma unroll
        for (int p = 0; p < 2; p++) {
            int row = rloc + mi * 16 + p * 8;
            #pragma unroll
            for (int nj = 0; nj < 8; nj++) {
                buf[row * 257 + cbase + nj * 8]     = acc[mi][nj][p * 2]     * inv[mi][p] * scl[nj][0];
                buf[row * 257 + cbase + nj * 8 + 1] = acc[mi][nj][p * 2 + 1] * inv[mi][p] * scl[nj][1];
            }
        }
    __syncthreads();

    #pragma unroll
    for (int mi = 0; mi < 4; mi++)
        #pragma unroll
        for (int p = 0; p < 2; p++) {
            int row = rloc + mi * 16 + p * 8;
            int tok = m0 + row;
            const float* srow = g_sin + (size_t)tok * 128;
            const float* crow = g_cos + (size_t)tok * 128;
            size_t ob = (size_t)tok * ostride + obase + cbase;
            #pragma unroll
            for (int nj = 0; nj < 8; nj++) {
                #pragma unroll
                for (int e = 0; e < 2; e++) {
                    int col = cbase + nj * 8 + e;
                    float v  = buf[row * 257 + col];
                    float pr = buf[row * 257 + (col ^ 128)];
                    int t = col & 127;
                    float y = (col < 128) ? (v * crow[t] - pr * srow[t])
                                          : (v * crow[t] + pr * srow[t]);
                    __half hh = __float2half(y);
                    outH[ob + nj * 8 + e] = hh;
                    outL[ob + nj * 8 + e] = __float2half(y - __half2float(hh));
                }
            }
        }
}

// ---------------- tensor-core sliding-window attention (fp16) ----------------
#define SWZ(row, colb) ((uint32_t)((row) * 512 + ((colb) ^ (((row) & 7) << 4))))
#define O_QH 0
#define O_QL 32768
#define O_KH 65536
#define O_KL 98304
#define O_VH 131072
#define O_PH 163840
#define O_SM  (O_PH + 9216)
#define O_SLN (O_SM + 256)
#define O_RM  (O_SLN + 256)
#define O_RS  (O_RM + 512)
#define ATT2_SMEM (O_RS + 512)
#define MASKV (-10000.0f)

__global__ __launch_bounds__(256, 1)
void attn_mma() {
    extern __shared__ char smem[];
    const uint32_t sb = smem_u32(smem);
    const int tid = threadIdx.x, lane = tid & 31, w = tid >> 5;
    const int wm = w & 3, wn = w >> 2;
    const int qb = blockIdx.x, q0 = qb << 6;
    const int h = blockIdx.y, khd = h >> 2;

    float* sm_m = (float*)(smem + O_SM);
    float* sm_l = (float*)(smem + O_SLN);
    float* red_m = (float*)(smem + O_RM);
    float* red_s = (float*)(smem + O_RS);

    if (tid < 64) { sm_m[tid] = MASKV; sm_l[tid] = 0.0f; }

    {
        const __half* qh = g_qh + (size_t)q0 * DIM + h * HDIM;
        const __half* ql = g_ql + (size_t)q0 * DIM + h * HDIM;
        #pragma unroll
        for (int it = 0; it < 8; it++) {
            int u = it * 256 + tid, row = u >> 5, colb = (u & 31) * 16;
            uint32_t swo = SWZ(row, colb);
            cp16(sb + O_QH + swo, (const char*)(qh + (size_t)row * DIM) + colb);
            cp16(sb + O_QL + swo, (const char*)(ql + (size_t)row * DIM) + colb);
        }
    }
    asm volatile("cp.async.commit_group;" ::: "memory");

    const int arow = wm * 16 + (lane & 15);
    const uint32_t acolx = (uint32_t)((lane >> 4) << 4);
    const int r0 = wm * 16 + (lane >> 2);

    float acc_o[16][4];
    #pragma unroll
    for (int nf = 0; nf < 16; nf++)
        #pragma unroll
        for (int e = 0; e < 4; e++) acc_o[nf][e] = 0.0f;

    const int kb_lo = (qb >= 8) ? qb - 8 : 0;

    for (int kb = kb_lo; kb <= qb; kb++) {
        const int k0 = kb << 6;
        __syncthreads();

        #pragma unroll
        for (int it = 0; it < 8; it++) {
            int u = it * 256 + tid, row = u >> 5, colb = (u & 31) * 16;
            size_t gro = (size_t)(k0 + row) * KVD + khd * HDIM;
            uint32_t swo = SWZ(row, colb);
            cp16(sb + O_KH + swo, (const char*)(g_kh + gro) + colb);
            cp16(sb + O_KL + swo, (const char*)(g_kl + gro) + colb);
            cp16(sb + O_VH + swo, (const char*)(g_vh + gro) + colb);
        }
        asm volatile("cp.async.commit_group;" ::: "memory");
        asm volatile("cp.async.wait_group 0;" ::: "memory");
        __syncthreads();

        float s[4][4];
        #pragma unroll
        for (int nf = 0; nf < 4; nf++)
            #pragma unroll
            for (int e = 0; e < 4; e++) s[nf][e] = 0.0f;

        #pragma unroll
        for (int ks = 0; ks < 16; ks++) {
            uint32_t ah[4], al_[4];
            ldm4(sb + O_QH + SWZ(arow, ks * 32 + acolx), ah);
            ldm4(sb + O_QL + SWZ(arow, ks * 32 + acolx), al_);
            #pragma unroll
            for (int ni = 0; ni < 2; ni++) {
                int brow = wn * 32 + ni * 16 + (lane & 7) + ((lane >> 4) << 3);
                uint32_t bcolb = (uint32_t)(ks * 32 + (((lane >> 3) & 1) << 4));
                uint32_t bh[4], bl[4];
                ldm4(sb + O_KH + SWZ(brow, bcolb), bh);
                ldm4(sb + O_KL + SWZ(brow, bcolb), bl);
                mma_h(s[ni * 2 + 0], ah, bh[0], bh[1]);
                mma_h(s[ni * 2 + 1], ah, bh[2], bh[3]);
                mma_h(s[ni * 2 + 0], al_, bh[0], bh[1]);
                mma_h(s[ni * 2 + 1], al_, bh[2], bh[3]);
                mma_h(s[ni * 2 + 0], ah, bl[0], bl[1]);
                mma_h(s[ni * 2 + 1], ah, bl[2], bl[3]);
            }
        }

        if (kb == qb) {
            #pragma unroll
            for (int nf = 0; nf < 4; nf++) {
                int keyc = k0 + wn * 32 + nf * 8 + (lane & 3) * 2;
                #pragma unroll
                for (int e = 0; e < 2; e++) {
                    if (keyc + e > q0 + r0)     s[nf][e]     = MASKV;
                    if (keyc + e > q0 + r0 + 8) s[nf][2 + e] = MASKV;
                }
            }
        }
        if (kb == kb_lo && qb >= 8) {
            #pragma unroll
            for (int nf = 0; nf < 4; nf++) {
                int keyc = k0 + wn * 32 + nf * 8 + (lane & 3) * 2;
                #pragma unroll
                for (int e = 0; e < 2; e++) {
                    if (keyc + e < q0 + r0 - (WIN - 1))     s[nf][e]     = MASKV;
                    if (keyc + e < q0 + r0 + 8 - (WIN - 1)) s[nf][2 + e] = MASKV;
                }
            }
        }

        float rm0 = -3.0e38f, rm1 = -3.0e38f;
        #pragma unroll
        for (int nf = 0; nf < 4; nf++) {
            rm0 = fmaxf(rm0, fmaxf(s[nf][0], s[nf][1]));
            rm1 = fmaxf(rm1, fmaxf(s[nf][2], s[nf][3]));
        }
        rm0 = fmaxf(rm0, __shfl_xor_sync(0xffffffffu, rm0, 1));
        rm0 = fmaxf(rm0, __shfl_xor_sync(0xffffffffu, rm0, 2));
        rm1 = fmaxf(rm1, __shfl_xor_sync(0xffffffffu, rm1, 1));
        rm1 = fmaxf(rm1, __shfl_xor_sync(0xffffffffu, rm1, 2));
        if ((lane & 3) == 0) {
            red_m[wn * 64 + r0]     = rm0;
            red_m[wn * 64 + r0 + 8] = rm1;
        }
        __syncthreads();

        float mo0 = sm_m[r0], mo1 = sm_m[r0 + 8];
        float mn0 = fmaxf(fmaxf(red_m[r0], red_m[64 + r0]), mo0);
        float mn1 = fmaxf(fmaxf(red_m[r0 + 8], red_m[64 + r0 + 8]), mo1);
        __syncthreads();
        if (wn == 0 && (lane & 3) == 0) { sm_m[r0] = mn0; sm_m[r0 + 8] = mn1; }
        float alpha0 = __expf(mo0 - mn0);
        float alpha1 = __expf(mo1 - mn1);

        float ls0 = 0.0f, ls1 = 0.0f;
        #pragma unroll
        for (int nf = 0; nf < 4; nf++) {
            float p0 = __expf(s[nf][0] - mn0);
            float p1 = __expf(s[nf][1] - mn0);
            float p2 = __expf(s[nf][2] - mn1);
            float p3 = __expf(s[nf][3] - mn1);
            ls0 += p0 + p1;
            ls1 += p2 + p3;
            uint32_t colb2 = (uint32_t)((wn * 32 + nf * 8 + (lane & 3) * 2) * 2);
            *(__half2*)(smem + O_PH + r0 * 144 + colb2) =
                __halves2half2(__float2half(p0), __float2half(p1));
            *(__half2*)(smem + O_PH + (r0 + 8) * 144 + colb2) =
                __halves2half2(__float2half(p2), __float2half(p3));
        }
        ls0 += __shfl_xor_sync(0xffffffffu, ls0, 1);
        ls0 += __shfl_xor_sync(0xffffffffu, ls0, 2);
        ls1 += __shfl_xor_sync(0xffffffffu, ls1, 1);
        ls1 += __shfl_xor_sync(0xffffffffu, ls1, 2);
        if ((lane & 3) == 0) {
            red_s[wn * 64 + r0]     = ls0;
            red_s[wn * 64 + r0 + 8] = ls1;
        }

        #pragma unroll
        for (int nf = 0; nf < 16; nf++) {
            acc_o[nf][0] *= alpha0;
            acc_o[nf][1] *= alpha0;
            acc_o[nf][2] *= alpha1;
            acc_o[nf][3] *= alpha1;
        }
        __syncthreads();
        if (wn == 0 && (lane & 3) == 0) {
            sm_l[r0]     = sm_l[r0] * alpha0 + red_s[r0] + red_s[64 + r0];
            sm_l[r0 + 8] = sm_l[r0 + 8] * alpha1 + red_s[r0 + 8] + red_s[64 + r0 + 8];
        }

        #pragma unroll
        for (int ks = 0; ks < 4; ks++) {
            uint32_t pah[4];
            ldm4(sb + O_PH + (uint32_t)(arow * 144 + ks * 32) + acolx, pah);
            #pragma unroll
            for (int ng = 0; ng < 8; ng++) {
                int vkrow = ks * 16 + (lane & 7) + (((lane >> 3) & 1) << 3);
                uint32_t vcolb = (uint32_t)((wn * 128 + ng * 16 + (((lane >> 4) & 1) << 3)) * 2);
                uint32_t vh[4];
                ldm4t(sb + O_VH + SWZ(vkrow, vcolb), vh);
                mma_h(acc_o[ng * 2 + 0], pah, vh[0], vh[1]);
                mma_h(acc_o[ng * 2 + 1], pah, vh[2], vh[3]);
            }
        }
    }

    __syncthreads();
    const float inv0 = 1.0f / sm_l[r0];
    const float inv1 = 1.0f / sm_l[r0 + 8];
    const size_t tok0 = (size_t)(q0 + r0) * DIM + h * HDIM;
    const size_t tok1 = (size_t)(q0 + r0 + 8) * DIM + h * HDIM;
    #pragma unroll
    for (int nf = 0; nf < 16; nf++) {
        int col = wn * 128 + nf * 8 + (lane & 3) * 2;
        *(__half2*)(g_ah + tok0 + col) =
            __halves2half2(__float2half(acc_o[nf][0] * inv0), __float2half(acc_o[nf][1] * inv0));
        *(__half2*)(g_ah + tok1 + col) =
            __halves2half2(__float2half(acc_o[nf][2] * inv1), __float2half(acc_o[nf][3] * inv1));
    }
}

// ---------------------------------------------------------------------------
extern "C" void kernel_launch(void* const* d_in, const int* in_sizes, int n_in,
                              void* d_out, int out_size) {
    const float* x         = (const float*)d_in[0];
    const int*   positions = (const int*)d_in[1];
    const float* Wq        = (const float*)d_in[2];
    const float* Wk        = (const float*)d_in[3];
    const float* Wv        = (const float*)d_in[4];
    const float* Wo        = (const float*)d_in[5];
    const float* q_scale   = (const float*)d_in[6];
    const float* k_scale   = (const float*)d_in[7];
    float* out = (float*)d_out;

    __half *xh, *xl, *ah, *wh, *wl, *woh;
    cudaGetSymbolAddress((void**)&xh, g_xh);
    cudaGetSymbolAddress((void**)&xl, g_xl);
    cudaGetSymbolAddress((void**)&ah, g_ah);
    cudaGetSymbolAddress((void**)&wh, g_wh);
    cudaGetSymbolAddress((void**)&wl, g_wl);
    cudaGetSymbolAddress((void**)&woh, g_woh);

    cudaFuncSetAttribute((const void*)gemm_h<3, true>,
                         cudaFuncAttributeMaxDynamicSharedMemorySize, 2 * 110592);
    cudaFuncSetAttribute((const void*)gemm_h<1, false>,
                         cudaFuncAttributeMaxDynamicSharedMemorySize, 2 * 55296);
    cudaFuncSetAttribute(attn_mma, cudaFuncAttributeMaxDynamicSharedMemorySize, ATT2_SMEM);

    const int n4 = SL * DIM / 4;

    // splits + rope table
    split_kernel<<<n4 / 256, 256>>>(x, xh, xl, n4);
    splitT_kernel<true><<<dim3(DIM / 32, DIM / 32), dim3(32, 8)>>>(Wq, wh, wl, DIM, DIM);
    splitT_kernel<true><<<dim3(KVD / 32, DIM / 32), dim3(32, 8)>>>(
        Wk, wh + (size_t)2048 * DIM, wl + (size_t)2048 * DIM, DIM, KVD);
    splitT_kernel<true><<<dim3(KVD / 32, DIM / 32), dim3(32, 8)>>>(
        Wv, wh + (size_t)2560 * DIM, wl + (size_t)2560 * DIM, DIM, KVD);
    splitT_kernel<false><<<dim3(DIM / 32, DIM / 32), dim3(32, 8)>>>(Wo, woh, nullptr, DIM, DIM);
    rope_table_kernel<<<SL * 128 / 256, 256>>>(positions);

    // fused QKV projection + RMSNorm + RoPE + split (3-term fp16)
    gemm_h<3, true><<<dim3(QKVN / 256, SL / 128), 256, 2 * 110592>>>(
        xh, xl, wh, wl, nullptr, 0, positions, q_scale, k_scale);

    // attention (QK 3-term, PV 1-term)
    attn_mma<<<dim3(SL / 64, NH), 256, ATT2_SMEM>>>();

    // output projection (1-term fp16)
    gemm_h<1, false><<<dim3(DIM / 256, SL / 128), 256, 2 * 55296>>>(
        ah, nullptr, woh, nullptr, out, DIM, nullptr, nullptr, nullptr);
}

// round 15
// speedup vs baseline: 1.6753x; 1.6753x over previous
#include <cuda_runtime.h>
#include <cuda_fp16.h>
#include <math.h>
#include <stdint.h>

#define SL   4096
#define DIM  2048
#define NH   8
#define NKV  2
#define HDIM 256
#define WIN  512
#define KVD  512
#define QKVN 3072   // packed Q|K|V output width

// ---------------- scratch ----------------
__device__ float g_qkv[SL * QKVN];          // fp32 packed projection output
__device__ __half g_xh[SL * DIM],  g_xl[SL * DIM];
__device__ __half g_qh[SL * DIM],  g_ql[SL * DIM];
__device__ __half g_kh[SL * KVD],  g_kl[SL * KVD];
__device__ __half g_vh[SL * KVD];
__device__ __half g_ah[SL * DIM];
__device__ __half g_wh[QKVN * DIM], g_wl[QKVN * DIM];   // packed Wq|Wk|Wv (transposed)
__device__ __half g_woh[DIM * DIM];
__device__ float  g_sin[SL * 128], g_cos[SL * 128];

__device__ __forceinline__ uint32_t smem_u32(const void* p) {
    uint32_t a;
    asm("{ .reg .u64 t; cvta.to.shared.u64 t, %1; cvt.u32.u64 %0, t; }" : "=r"(a) : "l"(p));
    return a;
}
__device__ __forceinline__ void cp16(uint32_t dst, const void* src) {
    asm volatile("cp.async.cg.shared.global [%0], [%1], 16;" :: "r"(dst), "l"(src) : "memory");
}
__device__ __forceinline__ void ldm4(uint32_t a, uint32_t r[4]) {
    asm volatile("ldmatrix.sync.aligned.m8n8.x4.shared.b16 {%0,%1,%2,%3}, [%4];"
                 : "=r"(r[0]), "=r"(r[1]), "=r"(r[2]), "=r"(r[3]) : "r"(a));
}
__device__ __forceinline__ void ldm4t(uint32_t a, uint32_t r[4]) {
    asm volatile("ldmatrix.sync.aligned.m8n8.x4.trans.shared.b16 {%0,%1,%2,%3}, [%4];"
                 : "=r"(r[0]), "=r"(r[1]), "=r"(r[2]), "=r"(r[3]) : "r"(a));
}
__device__ __forceinline__ void mma_h(float c[4], const uint32_t a[4], uint32_t b0, uint32_t b1) {
    asm volatile("mma.sync.aligned.m16n8k16.row.col.f32.f16.f16.f32 "
                 "{%0,%1,%2,%3}, {%4,%5,%6,%7}, {%8,%9}, {%0,%1,%2,%3};"
                 : "+f"(c[0]), "+f"(c[1]), "+f"(c[2]), "+f"(c[3])
                 : "r"(a[0]), "r"(a[1]), "r"(a[2]), "r"(a[3]), "r"(b0), "r"(b1));
}

// ---------------- conversion / table kernels ----------------
__global__ void split_kernel(const float* __restrict__ src,
                             __half* __restrict__ hi, __half* __restrict__ lo, int n4) {
    int i = blockIdx.x * blockDim.x + threadIdx.x;
    if (i >= n4) return;
    float4 v = ((const float4*)src)[i];
    float f[4] = {v.x, v.y, v.z, v.w};
    __half h[4], l[4];
    #pragma unroll
    for (int j = 0; j < 4; j++) {
        h[j] = __float2half(f[j]);
        l[j] = __float2half(f[j] - __half2float(h[j]));
    }
    __half2* h2 = (__half2*)hi;
    __half2* l2 = (__half2*)lo;
    h2[2 * i + 0] = __halves2half2(h[0], h[1]);
    h2[2 * i + 1] = __halves2half2(h[2], h[3]);
    l2[2 * i + 0] = __halves2half2(l[0], l[1]);
    l2[2 * i + 1] = __halves2half2(l[2], l[3]);
}

template<bool WLO>
__global__ void splitT_kernel(const float* __restrict__ src,
                              __half* __restrict__ hi, __half* __restrict__ lo, int K, int N) {
    __shared__ float t[32][33];
    const int tx = threadIdx.x, ty = threadIdx.y;
    const int n0 = blockIdx.x * 32, k0 = blockIdx.y * 32;
    #pragma unroll
    for (int i = 0; i < 32; i += 8)
        t[ty + i][tx] = src[(size_t)(k0 + ty + i) * N + n0 + tx];
    __syncthreads();
    #pragma unroll
    for (int i = 0; i < 32; i += 8) {
        float v = t[tx][ty + i];
        __half h = __float2half(v);
        size_t o = (size_t)(n0 + ty + i) * K + k0 + tx;
        hi[o] = h;
        if (WLO) lo[o] = __float2half(v - __half2float(h));
    }
}

__global__ void rope_table_kernel(const int* __restrict__ positions) {
    int idx = blockIdx.x * 256 + threadIdx.x;   // [0, SL*128)
    int t   = idx & 127;
    int tok = idx >> 7;
    float pos = (float)positions[tok];
    float timescale = powf(10000.0f, (float)t * (1.0f / 128.0f));
    float sv, cv;
    sincosf(pos / timescale, &sv, &cv);
    g_sin[idx] = sv;
    g_cos[idx] = cv;
}

// ---------------- fp16 mma GEMM: C[M,N] = A[M,2048] @ B[N,2048]^T ----------------
// 128x256 block tile, 8 warps (2m x 4n, 64x64 each), K-chunk 64, 2-stage cp.async.
#define GBK 64

template<int TERMS>
__device__ __forceinline__ void gh_load(uint32_t st,
                                        const __half* __restrict__ Ah, const __half* __restrict__ Al,
                                        const __half* __restrict__ Bh, const __half* __restrict__ Bl,
                                        int m0, int n0, int kc) {
    constexpr int AOFFL = 18432;
    constexpr int BOFF  = (TERMS == 3) ? 36864 : 18432;
    constexpr int BOFFL = 73728;
    const int tid = threadIdx.x;
    #pragma unroll
    for (int it = 0; it < 4; it++) {
        int u = it * 256 + tid, row = u >> 3, cb = (u & 7) * 16;
        cp16(st + row * 144 + cb, (const char*)(Ah + (size_t)(m0 + row) * DIM + kc) + cb);
        if (TERMS == 3)
            cp16(st + AOFFL + row * 144 + cb, (const char*)(Al + (size_t)(m0 + row) * DIM + kc) + cb);
    }
    #pragma unroll
    for (int it = 0; it < 8; it++) {
        int u = it * 256 + tid, row = u >> 3, cb = (u & 7) * 16;
        cp16(st + BOFF + row * 144 + cb, (const char*)(Bh + (size_t)(n0 + row) * DIM + kc) + cb);
        if (TERMS == 3)
            cp16(st + BOFFL + row * 144 + cb, (const char*)(Bl + (size_t)(n0 + row) * DIM + kc) + cb);
    }
}

template<int TERMS>
__global__ __launch_bounds__(256, 1)
void gemm_h(const __half* __restrict__ Ah, const __half* __restrict__ Al,
            const __half* __restrict__ Bh, const __half* __restrict__ Bl,
            float* __restrict__ C, int Nld) {
    constexpr int AOFFL = 18432;
    constexpr int BOFF  = (TERMS == 3) ? 36864 : 18432;
    constexpr int BOFFL = 73728;
    constexpr int STG   = (TERMS == 3) ? 110592 : 55296;
    extern __shared__ char smem[];
    const uint32_t sb = smem_u32(smem);
    const int tid = threadIdx.x, lane = tid & 31, w = tid >> 5;
    const int wmi = w >> 2, wni = w & 3;
    const int m0 = blockIdx.y * 128, n0 = blockIdx.x * 256;

    uint32_t a_off[4], b_off[4];
    #pragma unroll
    for (int mi = 0; mi < 4; mi++)
        a_off[mi] = (uint32_t)((wmi * 64 + mi * 16 + (lane & 15)) * 144 + ((lane >> 4) << 4));
    #pragma unroll
    for (int ni = 0; ni < 4; ni++)
        b_off[ni] = (uint32_t)((wni * 64 + ni * 16 + (lane & 7) + ((lane >> 4) << 3)) * 144
                               + (((lane >> 3) & 1) << 4));

    float acc[4][8][4];
    #pragma unroll
    for (int mi = 0; mi < 4; mi++)
        #pragma unroll
        for (int nj = 0; nj < 8; nj++)
            #pragma unroll
            for (int e = 0; e < 4; e++) acc[mi][nj][e] = 0.0f;

    const int nch = DIM / GBK;   // 32

    gh_load<TERMS>(sb, Ah, Al, Bh, Bl, m0, n0, 0);
    asm volatile("cp.async.commit_group;" ::: "memory");
    gh_load<TERMS>(sb + STG, Ah, Al, Bh, Bl, m0, n0, GBK);
    asm volatile("cp.async.commit_group;" ::: "memory");

    for (int c = 0; c < nch; c++) {
        if (c == nch - 1) asm volatile("cp.async.wait_group 0;" ::: "memory");
        else              asm volatile("cp.async.wait_group 1;" ::: "memory");
        __syncthreads();

        const uint32_t st = sb + (uint32_t)(c & 1) * STG;

        #pragma unroll
        for (int ks = 0; ks < 4; ks++) {
            const uint32_t kb = (uint32_t)(ks * 32);
            uint32_t ah[4][4], bh[4][4];
            uint32_t al[4][4], bl[4][4];
            #pragma unroll
            for (int mi = 0; mi < 4; mi++) {
                ldm4(st + a_off[mi] + kb, ah[mi]);
                if (TERMS == 3) ldm4(st + AOFFL + a_off[mi] + kb, al[mi]);
            }
            #pragma unroll
            for (int ni = 0; ni < 4; ni++) {
                ldm4(st + BOFF + b_off[ni] + kb, bh[ni]);
                if (TERMS == 3) ldm4(st + BOFFL + b_off[ni] + kb, bl[ni]);
            }
            #pragma unroll
            for (int mi = 0; mi < 4; mi++)
                #pragma unroll
                for (int ni = 0; ni < 4; ni++) {
                    mma_h(acc[mi][ni * 2 + 0], ah[mi], bh[ni][0], bh[ni][1]);
                    mma_h(acc[mi][ni * 2 + 1], ah[mi], bh[ni][2], bh[ni][3]);
                    if (TERMS == 3) {
                        mma_h(acc[mi][ni * 2 + 0], al[mi], bh[ni][0], bh[ni][1]);
                        mma_h(acc[mi][ni * 2 + 1], al[mi], bh[ni][2], bh[ni][3]);
                        mma_h(acc[mi][ni * 2 + 0], ah[mi], bl[ni][0], bl[ni][1]);
                        mma_h(acc[mi][ni * 2 + 1], ah[mi], bl[ni][2], bl[ni][3]);
                    }
                }
        }
        __syncthreads();
        if (c + 2 < nch) {
            gh_load<TERMS>(sb + (uint32_t)(c & 1) * STG, Ah, Al, Bh, Bl, m0, n0, (c + 2) * GBK);
            asm volatile("cp.async.commit_group;" ::: "memory");
        }
    }

    const int mbase = m0 + wmi * 64 + (lane >> 2);
    const int nbase = n0 + wni * 64 + (lane & 3) * 2;
    #pragma unroll
    for (int mi = 0; mi < 4; mi++)
        #pragma unroll
        for (int nj = 0; nj < 8; nj++) {
            float* p0 = C + (size_t)(mbase + mi * 16) * Nld + nbase + nj * 8;
            float* p1 = C + (size_t)(mbase + mi * 16 + 8) * Nld + nbase + nj * 8;
            *(float2*)p0 = make_float2(acc[mi][nj][0], acc[mi][nj][1]);
            *(float2*)p1 = make_float2(acc[mi][nj][2], acc[mi][nj][3]);
        }
}

// ---------------- RMSNorm + RoPE (table) -> fp16 hi/lo ----------------
__global__ void norm_rope_kernel(const float* __restrict__ q_scale,
                                 const float* __restrict__ k_scale) {
    const int token = blockIdx.x;
    const int which = blockIdx.y;
    const float* base;
    __half *oh, *ol = nullptr;
    const float* scale = nullptr;
    bool do_rope = true;
    if (which < 8) {
        base = g_qkv + (size_t)token * QKVN + which * HDIM;
        oh = g_qh + (size_t)token * DIM + which * HDIM;
        ol = g_ql + (size_t)token * DIM + which * HDIM;
        scale = q_scale;
    } else if (which < 10) {
        base = g_qkv + (size_t)token * QKVN + 2048 + (which - 8) * HDIM;
        oh = g_kh + (size_t)token * KVD + (which - 8) * HDIM;
        ol = g_kl + (size_t)token * KVD + (which - 8) * HDIM;
        scale = k_scale;
    } else {
        base = g_qkv + (size_t)token * QKVN + 2560 + (which - 10) * HDIM;
        oh = g_vh + (size_t)token * KVD + (which - 10) * HDIM;
        do_rope = false;
    }

    const int t = threadIdx.x;
    float x1 = base[t];
    float x2 = base[t + 128];

    float ss = x1 * x1 + x2 * x2;
    #pragma unroll
    for (int off = 16; off > 0; off >>= 1)
        ss += __shfl_xor_sync(0xffffffffu, ss, off);
    __shared__ float red[4];
    if ((t & 31) == 0) red[t >> 5] = ss;
    __syncthreads();
    ss = red[0] + red[1] + red[2] + red[3];

    float inv = rsqrtf(ss * (1.0f / 256.0f) + 1e-6f);
    x1 *= inv;
    x2 *= inv;
    if (scale) { x1 *= scale[t]; x2 *= scale[t + 128]; }

    float y1, y2;
    if (do_rope) {
        float sv = g_sin[(size_t)token * 128 + t];
        float cv = g_cos[(size_t)token * 128 + t];
        y1 = x1 * cv - x2 * sv;
        y2 = x2 * cv + x1 * sv;
    } else {
        y1 = x1; y2 = x2;
    }
    __half h1 = __float2half(y1);
    __half h2 = __float2half(y2);
    oh[t] = h1;
    oh[t + 128] = h2;
    if (ol) {
        ol[t]       = __float2half(y1 - __half2float(h1));
        ol[t + 128] = __float2half(y2 - __half2float(h2));
    }
}

// ---------------- tensor-core sliding-window attention (fp16, pipelined) -----
// 64q x 64k tiles; QK 3-term, PV 1-term. K load overlaps PV; V load overlaps scores.
#define SWZ(row, colb) ((uint32_t)((row) * 512 + ((colb) ^ (((row) & 7) << 4))))
#define O_QH 0
#define O_QL 32768
#define O_KH 65536
#define O_KL 98304
#define O_VH 131072
#define O_PH 163840
#define O_SM  (O_PH + 9216)
#define O_SLN (O_SM + 256)
#define O_RM  (O_SLN + 256)
#define O_RS  (O_RM + 512)
#define ATT2_SMEM (O_RS + 512)
#define MASKV (-10000.0f)

__device__ __forceinline__ void att_load_k(uint32_t sb, int k0, int khd, int tid) {
    #pragma unroll
    for (int it = 0; it < 8; it++) {
        int u = it * 256 + tid, row = u >> 5, colb = (u & 31) * 16;
        size_t gro = (size_t)(k0 + row) * KVD + khd * HDIM;
        uint32_t swo = SWZ(row, colb);
        cp16(sb + O_KH + swo, (const char*)(g_kh + gro) + colb);
        cp16(sb + O_KL + swo, (const char*)(g_kl + gro) + colb);
    }
}
__device__ __forceinline__ void att_load_v(uint32_t sb, int k0, int khd, int tid) {
    #pragma unroll
    for (int it = 0; it < 8; it++) {
        int u = it * 256 + tid, row = u >> 5, colb = (u & 31) * 16;
        size_t gro = (size_t)(k0 + row) * KVD + khd * HDIM;
        cp16(sb + O_VH + SWZ(row, colb), (const char*)(g_vh + gro) + colb);
    }
}

__global__ __launch_bounds__(256, 1)
void attn_mma() {
    extern __shared__ char smem[];
    const uint32_t sb = smem_u32(smem);
    const int tid = threadIdx.x, lane = tid & 31, w = tid >> 5;
    const int wm = w & 3, wn = w >> 2;
    const int qb = blockIdx.x, q0 = qb << 6;
    const int h = blockIdx.y, khd = h >> 2;

    float* sm_m = (float*)(smem + O_SM);
    float* sm_l = (float*)(smem + O_SLN);
    float* red_m = (float*)(smem + O_RM);
    float* red_s = (float*)(smem + O_RS);

    if (tid < 64) { sm_m[tid] = MASKV; sm_l[tid] = 0.0f; }

    const int kb_lo = (qb >= 8) ? qb - 8 : 0;

    // prologue: Q + first K in group0, first V in group1
    {
        const __half* qh = g_qh + (size_t)q0 * DIM + h * HDIM;
        const __half* ql = g_ql + (size_t)q0 * DIM + h * HDIM;
        #pragma unroll
        for (int it = 0; it < 8; it++) {
            int u = it * 256 + tid, row = u >> 5, colb = (u & 31) * 16;
            uint32_t swo = SWZ(row, colb);
            cp16(sb + O_QH + swo, (const char*)(qh + (size_t)row * DIM) + colb);
            cp16(sb + O_QL + swo, (const char*)(ql + (size_t)row * DIM) + colb);
        }
    }
    att_load_k(sb, kb_lo << 6, khd, tid);
    asm volatile("cp.async.commit_group;" ::: "memory");
    att_load_v(sb, kb_lo << 6, khd, tid);
    asm volatile("cp.async.commit_group;" ::: "memory");

    const int arow = wm * 16 + (lane & 15);
    const uint32_t acolx = (uint32_t)((lane >> 4) << 4);
    const int r0 = wm * 16 + (lane >> 2);

    float acc_o[16][4];
    #pragma unroll
    for (int nf = 0; nf < 16; nf++)
        #pragma unroll
        for (int e = 0; e < 4; e++) acc_o[nf][e] = 0.0f;

    for (int kb = kb_lo; kb <= qb; kb++) {
        const int k0 = kb << 6;

        // K_kb (and Q on first iter) ready; V_kb may still be in flight
        asm volatile("cp.async.wait_group 1;" ::: "memory");
        __syncthreads();

        // ---- scores: S = Q K^T (3-term) ----
        float s[4][4];
        #pragma unroll
        for (int nf = 0; nf < 4; nf++)
            #pragma unroll
            for (int e = 0; e < 4; e++) s[nf][e] = 0.0f;

        #pragma unroll
        for (int ks = 0; ks < 16; ks++) {
            uint32_t ah[4], al_[4];
            ldm4(sb + O_QH + SWZ(arow, ks * 32 + acolx), ah);
            ldm4(sb + O_QL + SWZ(arow, ks * 32 + acolx), al_);
            #pragma unroll
            for (int ni = 0; ni < 2; ni++) {
                int brow = wn * 32 + ni * 16 + (lane & 7) + ((lane >> 4) << 3);
                uint32_t bcolb = (uint32_t)(ks * 32 + (((lane >> 3) & 1) << 4));
                uint32_t bh[4], bl[4];
                ldm4(sb + O_KH + SWZ(brow, bcolb), bh);
                ldm4(sb + O_KL + SWZ(brow, bcolb), bl);
                mma_h(s[ni * 2 + 0], ah, bh[0], bh[1]);
                mma_h(s[ni * 2 + 1], ah, bh[2], bh[3]);
                mma_h(s[ni * 2 + 0], al_, bh[0], bh[1]);
                mma_h(s[ni * 2 + 1], al_, bh[2], bh[3]);
                mma_h(s[ni * 2 + 0], ah, bl[0], bl[1]);
                mma_h(s[ni * 2 + 1], ah, bl[2], bl[3]);
            }
        }

        // ---- masking ----
        if (kb == qb) {
            #pragma unroll
            for (int nf = 0; nf < 4; nf++) {
                int keyc = k0 + wn * 32 + nf * 8 + (lane & 3) * 2;
                #pragma unroll
                for (int e = 0; e < 2; e++) {
                    if (keyc + e > q0 + r0)     s[nf][e]     = MASKV;
                    if (keyc + e > q0 + r0 + 8) s[nf][2 + e] = MASKV;
                }
            }
        }
        if (kb == kb_lo && qb >= 8) {
            #pragma unroll
            for (int nf = 0; nf < 4; nf++) {
                int keyc = k0 + wn * 32 + nf * 8 + (lane & 3) * 2;
                #pragma unroll
                for (int e = 0; e < 2; e++) {
                    if (keyc + e < q0 + r0 - (WIN - 1))     s[nf][e]     = MASKV;
                    if (keyc + e < q0 + r0 + 8 - (WIN - 1)) s[nf][2 + e] = MASKV;
                }
            }
        }

        // ---- row max ----
        float rm0 = -3.0e38f, rm1 = -3.0e38f;
        #pragma unroll
        for (int nf = 0; nf < 4; nf++) {
            rm0 = fmaxf(rm0, fmaxf(s[nf][0], s[nf][1]));
            rm1 = fmaxf(rm1, fmaxf(s[nf][2], s[nf][3]));
        }
        rm0 = fmaxf(rm0, __shfl_xor_sync(0xffffffffu, rm0, 1));
        rm0 = fmaxf(rm0, __shfl_xor_sync(0xffffffffu, rm0, 2));
        rm1 = fmaxf(rm1, __shfl_xor_sync(0xffffffffu, rm1, 1));
        rm1 = fmaxf(rm1, __shfl_xor_sync(0xffffffffu, rm1, 2));
        if ((lane & 3) == 0) {
            red_m[wn * 64 + r0]     = rm0;
            red_m[wn * 64 + r0 + 8] = rm1;
        }
        __syncthreads();   // (A) — all K reads complete CTA-wide

        // K buffer free: prefetch next chunk's K (overlaps softmax + PV)
        if (kb < qb) {
            att_load_k(sb, (kb + 1) << 6, khd, tid);
            asm volatile("cp.async.commit_group;" ::: "memory");
        }

        float mo0 = sm_m[r0], mo1 = sm_m[r0 + 8];
        float mn0 = fmaxf(fmaxf(red_m[r0], red_m[64 + r0]), mo0);
        float mn1 = fmaxf(fmaxf(red_m[r0 + 8], red_m[64 + r0 + 8]), mo1);
        __syncthreads();   // (B) — everyone read sm_m before overwrite
        if (wn == 0 && (lane & 3) == 0) { sm_m[r0] = mn0; sm_m[r0 + 8] = mn1; }
        float alpha0 = __expf(mo0 - mn0);
        float alpha1 = __expf(mo1 - mn1);

        // ---- exp, row sums, P (hi only) ----
        float ls0 = 0.0f, ls1 = 0.0f;
        #pragma unroll
        for (int nf = 0; nf < 4; nf++) {
            float p0 = __expf(s[nf][0] - mn0);
            float p1 = __expf(s[nf][1] - mn0);
            float p2 = __expf(s[nf][2] - mn1);
            float p3 = __expf(s[nf][3] - mn1);
            ls0 += p0 + p1;
            ls1 += p2 + p3;
            uint32_t colb2 = (uint32_t)((wn * 32 + nf * 8 + (lane & 3) * 2) * 2);
            *(__half2*)(smem + O_PH + r0 * 144 + colb2) =
                __halves2half2(__float2half(p0), __float2half(p1));
            *(__half2*)(smem + O_PH + (r0 + 8) * 144 + colb2) =
                __halves2half2(__float2half(p2), __float2half(p3));
        }
        ls0 += __shfl_xor_sync(0xffffffffu, ls0, 1);
        ls0 += __shfl_xor_sync(0xffffffffu, ls0, 2);
        ls1 += __shfl_xor_sync(0xffffffffu, ls1, 1);
        ls1 += __shfl_xor_sync(0xffffffffu, ls1, 2);
        if ((lane & 3) == 0) {
            red_s[wn * 64 + r0]     = ls0;
            red_s[wn * 64 + r0 + 8] = ls1;
        }

        #pragma unroll
        for (int nf = 0; nf < 16; nf++) {
            acc_o[nf][0] *= alpha0;
            acc_o[nf][1] *= alpha0;
            acc_o[nf][2] *= alpha1;
            acc_o[nf][3] *= alpha1;
        }

        // V_kb must be complete (only newest group — next K — may be outstanding)
        if (kb < qb) asm volatile("cp.async.wait_group 1;" ::: "memory");
        else         asm volatile("cp.async.wait_group 0;" ::: "memory");
        __syncthreads();   // (C) — P, red_s, and V visible to all
        if (wn == 0 && (lane & 3) == 0) {
            sm_l[r0]     = sm_l[r0] * alpha0 + red_s[r0] + red_s[64 + r0];
            sm_l[r0 + 8] = sm_l[r0 + 8] * alpha1 + red_s[r0 + 8] + red_s[64 + r0 + 8];
        }

        // ---- O += P V (1-term) ----
        #pragma unroll
        for (int ks = 0; ks < 4; ks++) {
            uint32_t pah[4];
            ldm4(sb + O_PH + (uint32_t)(arow * 144 + ks * 32) + acolx, pah);
            #pragma unroll
            for (int ng = 0; ng < 8; ng++) {
                int vkrow = ks * 16 + (lane & 7) + (((lane >> 3) & 1) << 3);
                uint32_t vcolb = (uint32_t)((wn * 128 + ng * 16 + (((lane >> 4) & 1) << 3)) * 2);
                uint32_t vh[4];
                ldm4t(sb + O_VH + SWZ(vkrow, vcolb), vh);
                mma_h(acc_o[ng * 2 + 0], pah, vh[0], vh[1]);
                mma_h(acc_o[ng * 2 + 1], pah, vh[2], vh[3]);
            }
        }
        __syncthreads();   // (D) — all V reads complete CTA-wide

        // V buffer free: prefetch next chunk's V (overlaps next score phase)
        if (kb < qb) {
            att_load_v(sb, (kb + 1) << 6, khd, tid);
            asm volatile("cp.async.commit_group;" ::: "memory");
        }
    }

    const float inv0 = 1.0f / sm_l[r0];
    const float inv1 = 1.0f / sm_l[r0 + 8];
    const size_t tok0 = (size_t)(q0 + r0) * DIM + h * HDIM;
    const size_t tok1 = (size_t)(q0 + r0 + 8) * DIM + h * HDIM;
    #pragma unroll
    for (int nf = 0; nf < 16; nf++) {
        int col = wn * 128 + nf * 8 + (lane & 3) * 2;
        *(__half2*)(g_ah + tok0 + col) =
            __halves2half2(__float2half(acc_o[nf][0] * inv0), __float2half(acc_o[nf][1] * inv0));
        *(__half2*)(g_ah + tok1 + col) =
            __halves2half2(__float2half(acc_o[nf][2] * inv1), __float2half(acc_o[nf][3] * inv1));
    }
}

// ---------------------------------------------------------------------------
extern "C" void kernel_launch(void* const* d_in, const int* in_sizes, int n_in,
                              void* d_out, int out_size) {
    const float* x         = (const float*)d_in[0];
    const int*   positions = (const int*)d_in[1];
    const float* Wq        = (const float*)d_in[2];
    const float* Wk        = (const float*)d_in[3];
    const float* Wv        = (const float*)d_in[4];
    const float* Wo        = (const float*)d_in[5];
    const float* q_scale   = (const float*)d_in[6];
    const float* k_scale   = (const float*)d_in[7];
    float* out = (float*)d_out;

    float* qkvp;
    cudaGetSymbolAddress((void**)&qkvp, g_qkv);
    __half *xh, *xl, *ah, *wh, *wl, *woh;
    cudaGetSymbolAddress((void**)&xh, g_xh);
    cudaGetSymbolAddress((void**)&xl, g_xl);
    cudaGetSymbolAddress((void**)&ah, g_ah);
    cudaGetSymbolAddress((void**)&wh, g_wh);
    cudaGetSymbolAddress((void**)&wl, g_wl);
    cudaGetSymbolAddress((void**)&woh, g_woh);

    cudaFuncSetAttribute(gemm_h<3>, cudaFuncAttributeMaxDynamicSharedMemorySize, 2 * 110592);
    cudaFuncSetAttribute(gemm_h<1>, cudaFuncAttributeMaxDynamicSharedMemorySize, 2 * 55296);
    cudaFuncSetAttribute(attn_mma, cudaFuncAttributeMaxDynamicSharedMemorySize, ATT2_SMEM);

    const int n4 = SL * DIM / 4;

    // splits + rope table
    split_kernel<<<n4 / 256, 256>>>(x, xh, xl, n4);
    splitT_kernel<true><<<dim3(DIM / 32, DIM / 32), dim3(32, 8)>>>(Wq, wh, wl, DIM, DIM);
    splitT_kernel<true><<<dim3(KVD / 32, DIM / 32), dim3(32, 8)>>>(
        Wk, wh + (size_t)2048 * DIM, wl + (size_t)2048 * DIM, DIM, KVD);
    splitT_kernel<true><<<dim3(KVD / 32, DIM / 32), dim3(32, 8)>>>(
        Wv, wh + (size_t)2560 * DIM, wl + (size_t)2560 * DIM, DIM, KVD);
    splitT_kernel<false><<<dim3(DIM / 32, DIM / 32), dim3(32, 8)>>>(Wo, woh, nullptr, DIM, DIM);
    rope_table_kernel<<<SL * 128 / 256, 256>>>(positions);

    // fused QKV projection (3-term fp16)
    gemm_h<3><<<dim3(QKVN / 256, SL / 128), 256, 2 * 110592>>>(xh, xl, wh, wl, qkvp, QKVN);

    // RMSNorm + RoPE (table) -> fp16 hi/lo
    norm_rope_kernel<<<dim3(SL, 12), 128>>>(q_scale, k_scale);

    // attention (QK 3-term, PV 1-term, pipelined loads)
    attn_mma<<<dim3(SL / 64, NH), 256, ATT2_SMEM>>>();

    // output projection (1-term fp16)
    gemm_h<1><<<dim3(DIM / 256, SL / 128), 256, 2 * 55296>>>(ah, nullptr, woh, nullptr, out, DIM);
}